// round 4
// baseline (speedup 1.0000x reference)
#include <cuda_runtime.h>

// GRU: T=2048, B=64, IN=256, H=256, L=3
// Output = [seq (2048*64*256) floats][h_n (3*64*256) floats]
//
// Per layer:
//   Phase A: gemm_gx (fp32, f32x2-packed FFMA): g_gx = A @ Wih^T + bih
//   Phase B: gru_scan: 128 CTAs as 16 clusters of 8. Each cluster owns 4
//     batches; each CTA owns 32 hidden units (96 gate rows) register-resident.
//     h_t lives in SMEM (double-buffered), exchanged across the cluster via
//     st.shared::cluster + barrier.cluster each step. No global barrier,
//     no cross-cluster dependency.

#define T_STEPS 2048
#define B_SZ    64
#define H_SZ    256
#define G3      768
#define M_TOT   (T_STEPS * B_SZ)

typedef unsigned long long u64;

// ---------------- device scratch (no cudaMalloc allowed) -------------------
__device__ float g_gx[(size_t)M_TOT * G3];     // 402 MB input projections
__device__ float g_seq[(size_t)M_TOT * H_SZ];  // 134 MB inter-layer sequence

// ---------------- packed fp32 helpers ---------------------------------------
__device__ __forceinline__ void ffma2(u64 &d, u64 a, u64 b) {
    asm("fma.rn.f32x2 %0, %1, %2, %0;" : "+l"(d) : "l"(a), "l"(b));
}
__device__ __forceinline__ u64 pack2(float lo, float hi) {
    u64 r; asm("mov.b64 %0, {%1, %2};" : "=l"(r) : "f"(lo), "f"(hi)); return r;
}
__device__ __forceinline__ float2 unpack2(u64 v) {
    float2 r; asm("mov.b64 {%0, %1}, %2;" : "=f"(r.x), "=f"(r.y) : "l"(v)); return r;
}
__device__ __forceinline__ float fsigmoid(float x) {
    float e; asm("ex2.approx.f32 %0, %1;" : "=f"(e) : "f"(-1.4426950408889634f * x));
    float r; asm("rcp.approx.f32 %0, %1;" : "=f"(r) : "f"(1.0f + e));
    return r;
}
__device__ __forceinline__ float ftanh(float x) {
    float y; asm("tanh.approx.f32 %0, %1;" : "=f"(y) : "f"(x)); return y;
}
__device__ __forceinline__ unsigned mapa_shared(unsigned addr, unsigned rank) {
    unsigned r;
    asm("mapa.shared::cluster.u32 %0, %1, %2;" : "=r"(r) : "r"(addr), "r"(rank));
    return r;
}
__device__ __forceinline__ void st_cluster_u64(unsigned addr, u64 v) {
    asm volatile("st.shared::cluster.b64 [%0], %1;" :: "r"(addr), "l"(v) : "memory");
}

// ---------------- Phase A: gx GEMM  (C[M,768] = A[M,256] @ W[768,256]^T + b)
__global__ __launch_bounds__(256) void gemm_gx(
    const float* __restrict__ A,
    const float* __restrict__ W,
    const float* __restrict__ bias)
{
    __shared__ __align__(16) float As[32 * 132];   // [k][m], pitch 132
    __shared__ __align__(16) float Bs[32 * 64];    // [k][n]

    const int tid = threadIdx.x;
    const int tx  = tid & 15;        // n
    const int ty  = tid >> 4;        // m
    const int m0  = blockIdx.x * 128;
    const int n0  = blockIdx.y * 64;

    u64 acc[4][4];                   // [m-pair][n], each packs 2 m-rows
#pragma unroll
    for (int i = 0; i < 4; i++)
#pragma unroll
        for (int j = 0; j < 4; j++) acc[i][j] = 0ULL;

    for (int k0 = 0; k0 < 256; k0 += 32) {
#pragma unroll
        for (int i = 0; i < 4; i++) {             // A tile 128x32
            int f = tid + 256 * i;
            int r = f >> 3, c4 = f & 7;
            float4 v = *(const float4*)(A + (size_t)(m0 + r) * 256 + k0 + c4 * 4);
            As[(c4 * 4 + 0) * 132 + r] = v.x;
            As[(c4 * 4 + 1) * 132 + r] = v.y;
            As[(c4 * 4 + 2) * 132 + r] = v.z;
            As[(c4 * 4 + 3) * 132 + r] = v.w;
        }
#pragma unroll
        for (int i = 0; i < 2; i++) {             // W tile 64x32
            int f = tid + 256 * i;
            int r = f >> 3, c4 = f & 7;
            float4 v = *(const float4*)(W + (size_t)(n0 + r) * 256 + k0 + c4 * 4);
            Bs[(c4 * 4 + 0) * 64 + r] = v.x;
            Bs[(c4 * 4 + 1) * 64 + r] = v.y;
            Bs[(c4 * 4 + 2) * 64 + r] = v.z;
            Bs[(c4 * 4 + 3) * 64 + r] = v.w;
        }
        __syncthreads();

#pragma unroll
        for (int k = 0; k < 32; k++) {
            const u64* ap = (const u64*)&As[k * 132 + ty * 8];  // 4 packed m-pairs
            u64 a0 = ap[0], a1 = ap[1], a2 = ap[2], a3 = ap[3];
            float4 bv = *(const float4*)&Bs[k * 64 + tx * 4];
            u64 b0 = pack2(bv.x, bv.x);
            u64 b1 = pack2(bv.y, bv.y);
            u64 b2 = pack2(bv.z, bv.z);
            u64 b3 = pack2(bv.w, bv.w);
            ffma2(acc[0][0], a0, b0); ffma2(acc[0][1], a0, b1);
            ffma2(acc[0][2], a0, b2); ffma2(acc[0][3], a0, b3);
            ffma2(acc[1][0], a1, b0); ffma2(acc[1][1], a1, b1);
            ffma2(acc[1][2], a1, b2); ffma2(acc[1][3], a1, b3);
            ffma2(acc[2][0], a2, b0); ffma2(acc[2][1], a2, b1);
            ffma2(acc[2][2], a2, b2); ffma2(acc[2][3], a2, b3);
            ffma2(acc[3][0], a3, b0); ffma2(acc[3][1], a3, b1);
            ffma2(acc[3][2], a3, b2); ffma2(acc[3][3], a3, b3);
        }
        __syncthreads();
    }

    float4 bv = *(const float4*)(bias + n0 + tx * 4);
#pragma unroll
    for (int i = 0; i < 4; i++) {
        float2 c0 = unpack2(acc[i][0]);
        float2 c1 = unpack2(acc[i][1]);
        float2 c2 = unpack2(acc[i][2]);
        float2 c3 = unpack2(acc[i][3]);
        float4 e, o;
        e.x = c0.x + bv.x; e.y = c1.x + bv.y; e.z = c2.x + bv.z; e.w = c3.x + bv.w;
        o.x = c0.y + bv.x; o.y = c1.y + bv.y; o.z = c2.y + bv.z; o.w = c3.y + bv.w;
        *(float4*)(g_gx + (size_t)(m0 + ty * 8 + 2 * i)     * G3 + n0 + tx * 4) = e;
        *(float4*)(g_gx + (size_t)(m0 + ty * 8 + 2 * i + 1) * G3 + n0 + tx * 4) = o;
    }
}

// ---------------- Phase B: cluster-local recurrent scan ---------------------
// Grid 128, cluster 8 => 16 independent clusters. Cluster g owns batches
// [4g, 4g+4). CTA rank c owns units [32c, 32c+32) (96 gate rows) in regs.
// Thread (rg = tid>>4, ks = tid&15): units u0 = 32c + 2rg, k-slice
// {kk*64 + ks*4 + e}. Each step: 2 batch-pair passes of packed-k FFMA2,
// 16-lane shuffle reduce, combine lanes (ks<4, batch = ks) apply gates and
// broadcast h via st.shared::cluster, then barrier.cluster.
__global__ __launch_bounds__(256, 1) __cluster_dims__(8, 1, 1)
void gru_scan(const float* __restrict__ h0l,   // [64,256]
              const float* __restrict__ Whh,   // [768,256]
              const float* __restrict__ bhh,   // [768]
              float* __restrict__ seqout,      // [2048,64,256]
              float* __restrict__ hn_out)      // [64,256]
{
    __shared__ __align__(16) float hbuf[2][4][256];   // [buf][batch][unit]

    const int tid = threadIdx.x;
    const int rg  = tid >> 4;
    const int ks  = tid & 15;
    unsigned rank;
    asm("mov.u32 %0, %%cluster_ctarank;" : "=r"(rank));
    const int u0     = (int)rank * 32 + rg * 2;
    const int b_base = (blockIdx.x >> 3) * 4;

    int rows[6];
    rows[0] = u0;       rows[1] = u0 + 1;
    rows[2] = 256 + u0; rows[3] = 257 + u0;
    rows[4] = 512 + u0; rows[5] = 513 + u0;

    // Whh slice packed along k: wk[r][kk*2+p] covers k = kk*64+ks*4 + {2p,2p+1}
    u64 wk[6][8];
#pragma unroll
    for (int r = 0; r < 6; r++)
#pragma unroll
        for (int kk = 0; kk < 4; kk++) {
            float4 v = *(const float4*)(Whh + (size_t)rows[r] * 256 + kk * 64 + ks * 4);
            wk[r][kk * 2 + 0] = pack2(v.x, v.y);
            wk[r][kk * 2 + 1] = pack2(v.z, v.w);
        }
    float bh6[6];
#pragma unroll
    for (int r = 0; r < 6; r++) bh6[r] = bhh[rows[r]];

    // Fill hbuf[0] with h0 for our 4 batches (full 256 units each).
    {
        int bl = tid >> 6, off = (tid & 63) * 4;
        *(float4*)&hbuf[0][bl][off] = *(const float4*)&h0l[(b_base + bl) * 256 + off];
    }
    __syncthreads();

    // Peer SMEM base addresses for hbuf.
    unsigned hb_local = (unsigned)__cvta_generic_to_shared(&hbuf[0][0][0]);
    unsigned peer_base[8];
#pragma unroll
    for (int p = 0; p < 8; p++) peer_base[p] = mapa_shared(hb_local, (unsigned)p);

    const int  bl      = ks;          // combine lane's batch index (if < 4)
    const bool is_comb = (ks < 4);

    // Prefetch gx for t=0 (3 x b64: row pairs (r), (z), (n))
    u64 gxv0 = 0, gxv1 = 0, gxv2 = 0;
    if (is_comb) {
        const float* gp = g_gx + ((size_t)0 * B_SZ + b_base + bl) * G3;
        gxv0 = *(const u64*)(gp + u0);
        gxv1 = *(const u64*)(gp + 256 + u0);
        gxv2 = *(const u64*)(gp + 512 + u0);
    }

    for (int t = 0; t < T_STEPS; t++) {
        const int cur = t & 1, nxt = cur ^ 1;

#pragma unroll
        for (int bp = 0; bp < 2; bp++) {           // batch pair {2bp, 2bp+1}
            u64 acc[6][2];
#pragma unroll
            for (int r = 0; r < 6; r++) { acc[r][0] = 0ULL; acc[r][1] = 0ULL; }

#pragma unroll
            for (int kk = 0; kk < 4; kk++) {
                ulonglong2 hA = *(const ulonglong2*)&hbuf[cur][2 * bp + 0][kk * 64 + ks * 4];
                ulonglong2 hB = *(const ulonglong2*)&hbuf[cur][2 * bp + 1][kk * 64 + ks * 4];
#pragma unroll
                for (int r = 0; r < 6; r++) {
                    ffma2(acc[r][0], wk[r][kk * 2 + 0], hA.x);
                    ffma2(acc[r][0], wk[r][kk * 2 + 1], hA.y);
                    ffma2(acc[r][1], wk[r][kk * 2 + 0], hB.x);
                    ffma2(acc[r][1], wk[r][kk * 2 + 1], hB.y);
                }
            }

            // Collapse packed-k halves, then reduce over 16 k-slices.
            float sA[6], sB[6];
#pragma unroll
            for (int r = 0; r < 6; r++) {
                float2 a = unpack2(acc[r][0]); sA[r] = a.x + a.y;
                float2 b = unpack2(acc[r][1]); sB[r] = b.x + b.y;
            }
#pragma unroll
            for (int off = 1; off < 16; off <<= 1) {
#pragma unroll
                for (int r = 0; r < 6; r++) {
                    sA[r] += __shfl_xor_sync(0xFFFFFFFFu, sA[r], off);
                    sB[r] += __shfl_xor_sync(0xFFFFFFFFu, sB[r], off);
                }
            }

            // Combine lanes for this pass: bl in {2bp, 2bp+1}.
            if (is_comb && (bl >> 1) == bp) {
                float s0, s1, s2, s3, s4, s5;
                if (bl & 1) { s0=sB[0]; s1=sB[1]; s2=sB[2]; s3=sB[3]; s4=sB[4]; s5=sB[5]; }
                else        { s0=sA[0]; s1=sA[1]; s2=sA[2]; s3=sA[3]; s4=sA[4]; s5=sA[5]; }

                float hold0 = hbuf[cur][bl][u0];
                float hold1 = hbuf[cur][bl][u0 + 1];
                float2 gxr = unpack2(gxv0);
                float2 gxz = unpack2(gxv1);
                float2 gxn = unpack2(gxv2);

                float r0 = fsigmoid(gxr.x + s0 + bh6[0]);
                float z0 = fsigmoid(gxz.x + s2 + bh6[2]);
                float n0 = ftanh(gxn.x + r0 * (s4 + bh6[4]));
                float out0 = (1.0f - z0) * n0 + z0 * hold0;

                float r1 = fsigmoid(gxr.y + s1 + bh6[1]);
                float z1 = fsigmoid(gxz.y + s3 + bh6[3]);
                float n1 = ftanh(gxn.y + r1 * (s5 + bh6[5]));
                float out1 = (1.0f - z1) * n1 + z1 * hold1;

                u64 o = pack2(out0, out1);
                *(u64*)&seqout[((size_t)t * B_SZ + b_base + bl) * H_SZ + u0] = o;
                if (t == T_STEPS - 1)
                    *(u64*)&hn_out[(b_base + bl) * 256 + u0] = o;

                // Broadcast h_{t+1}[bl][u0..u0+1] to all 8 CTAs' hbuf[nxt].
                unsigned off8 = (unsigned)(((nxt * 4 + bl) * 256 + u0) * 4);
#pragma unroll
                for (int p = 0; p < 8; p++)
                    st_cluster_u64(peer_base[p] + off8, o);
            }
        }

        asm volatile("barrier.cluster.arrive.aligned;" ::: "memory");

        // Prefetch gx for t+1 while the cluster drains.
        if (is_comb && t + 1 < T_STEPS) {
            const float* gp = g_gx + ((size_t)(t + 1) * B_SZ + b_base + bl) * G3;
            gxv0 = *(const u64*)(gp + u0);
            gxv1 = *(const u64*)(gp + 256 + u0);
            gxv2 = *(const u64*)(gp + 512 + u0);
        }

        asm volatile("barrier.cluster.wait.aligned;" ::: "memory");
    }
}

// ---------------- launch -----------------------------------------------------
extern "C" void kernel_launch(void* const* d_in, const int* in_sizes, int n_in,
                              void* d_out, int out_size)
{
    const float* x   = (const float*)d_in[0];   // [2048,64,256]
    const float* h0  = (const float*)d_in[1];   // [3,64,256]
    const float* Wih = (const float*)d_in[2];   // [3,768,256]
    const float* Whh = (const float*)d_in[3];   // [3,768,256]
    const float* bih = (const float*)d_in[4];   // [3,768]
    const float* bhh = (const float*)d_in[5];   // [3,768]

    float* out     = (float*)d_out;
    float* hn_base = out + (size_t)T_STEPS * B_SZ * H_SZ;

    void* gseq_ptr = nullptr;
    cudaGetSymbolAddress(&gseq_ptr, g_seq);
    float* gseq = (float*)gseq_ptr;

    const dim3 ggrid(M_TOT / 128, G3 / 64);     // (1024, 12)
    const size_t WSTRIDE = (size_t)G3 * 256;
    const size_t HSTRIDE = (size_t)B_SZ * H_SZ;

    // ---- layer 0 ----
    gemm_gx<<<ggrid, 256>>>(x, Wih, bih);
    gru_scan<<<128, 256>>>(h0, Whh, bhh, gseq, hn_base);

    // ---- layer 1 ----
    gemm_gx<<<ggrid, 256>>>(gseq, Wih + WSTRIDE, bih + G3);
    gru_scan<<<128, 256>>>(h0 + HSTRIDE, Whh + WSTRIDE, bhh + G3,
                           gseq, hn_base + HSTRIDE);

    // ---- layer 2 (writes final sequence directly to d_out) ----
    gemm_gx<<<ggrid, 256>>>(gseq, Wih + 2 * WSTRIDE, bih + 2 * G3);
    gru_scan<<<128, 256>>>(h0 + 2 * HSTRIDE, Whh + 2 * WSTRIDE, bhh + 2 * G3,
                           out, hn_base + 2 * HSTRIDE);
}

// round 5
// speedup vs baseline: 1.2480x; 1.2480x over previous
#include <cuda_runtime.h>

// GRU: T=2048, B=64, IN=256, H=256, L=3
// Output = [seq (2048*64*256) floats][h_n (3*64*256) floats]
//
// R4 design:
//  - gru_scan: R2 structure (128 CTAs, 2 units/CTA, weights in regs, global
//    release/acquire barrier per step), FFMA2 (fma.rn.f32x2) inner loop,
//    chunked into 8 kernels of 256 steps per layer.
//  - gemm_gx: R2's fmaf SGEMM, chunked by timestep range (m_base param).
//  - kernel_launch builds a pipelined DAG: scans serial on the capture
//    stream; gemm chunks on a forked stream, event-gated per chunk, so the
//    GEMM work for layer l+1 overlaps the scan of layer l.

#define T_STEPS  2048
#define B_SZ     64
#define H_SZ     256
#define G3       768
#define M_TOT    (T_STEPS * B_SZ)
#define NCHUNK   8
#define CHUNK_T  (T_STEPS / NCHUNK)       // 256
#define CHUNK_M  (CHUNK_T * B_SZ)         // 16384

typedef unsigned long long u64;

// ---------------- device scratch (no cudaMalloc allowed) -------------------
__device__ float g_gx[(size_t)M_TOT * G3];     // 402 MB input projections
__device__ float g_seq[(size_t)M_TOT * H_SZ];  // 134 MB inter-layer sequence
__device__ unsigned int g_arrive3[3];

__global__ void reset_kernel() {
    g_arrive3[0] = 0u; g_arrive3[1] = 0u; g_arrive3[2] = 0u;
}

// ---------------- packed fp32 helpers ---------------------------------------
__device__ __forceinline__ void ffma2(u64 &d, u64 a, u64 b) {
    asm("fma.rn.f32x2 %0, %1, %2, %0;" : "+l"(d) : "l"(a), "l"(b));
}
__device__ __forceinline__ u64 pack2(float lo, float hi) {
    u64 r; asm("mov.b64 %0, {%1, %2};" : "=l"(r) : "f"(lo), "f"(hi)); return r;
}
__device__ __forceinline__ float2 unpack2(u64 v) {
    float2 r; asm("mov.b64 {%0, %1}, %2;" : "=f"(r.x), "=f"(r.y) : "l"(v)); return r;
}
__device__ __forceinline__ float fsigmoid(float x) {
    float e; asm("ex2.approx.f32 %0, %1;" : "=f"(e) : "f"(-1.4426950408889634f * x));
    float r; asm("rcp.approx.f32 %0, %1;" : "=f"(r) : "f"(1.0f + e));
    return r;
}
__device__ __forceinline__ float ftanh(float x) {
    float y; asm("tanh.approx.f32 %0, %1;" : "=f"(y) : "f"(x)); return y;
}

// ---------------- Phase A: gx GEMM  (chunked) -------------------------------
// C[m][n] = sum_k A[m][k]*W[n][k] + bias[n], m in [m_base, m_base+16384)
__global__ __launch_bounds__(256) void gemm_gx(
    const float* __restrict__ A,
    const float* __restrict__ W,
    const float* __restrict__ bias,
    int m_base)
{
    __shared__ __align__(16) float As[32 * 132];
    __shared__ __align__(16) float Bs[32 * 64];

    const int tid = threadIdx.x;
    const int tx  = tid & 15;
    const int ty  = tid >> 4;
    const int m0  = m_base + blockIdx.x * 128;
    const int n0  = blockIdx.y * 64;

    float acc[8][4];
#pragma unroll
    for (int i = 0; i < 8; i++)
#pragma unroll
        for (int j = 0; j < 4; j++) acc[i][j] = 0.0f;

    for (int k0 = 0; k0 < 256; k0 += 32) {
#pragma unroll
        for (int i = 0; i < 4; i++) {
            int f = tid + 256 * i;
            int r = f >> 3, c4 = f & 7;
            float4 v = *(const float4*)(A + (size_t)(m0 + r) * 256 + k0 + c4 * 4);
            As[(c4 * 4 + 0) * 132 + r] = v.x;
            As[(c4 * 4 + 1) * 132 + r] = v.y;
            As[(c4 * 4 + 2) * 132 + r] = v.z;
            As[(c4 * 4 + 3) * 132 + r] = v.w;
        }
#pragma unroll
        for (int i = 0; i < 2; i++) {
            int f = tid + 256 * i;
            int r = f >> 3, c4 = f & 7;
            float4 v = *(const float4*)(W + (size_t)(n0 + r) * 256 + k0 + c4 * 4);
            Bs[(c4 * 4 + 0) * 64 + r] = v.x;
            Bs[(c4 * 4 + 1) * 64 + r] = v.y;
            Bs[(c4 * 4 + 2) * 64 + r] = v.z;
            Bs[(c4 * 4 + 3) * 64 + r] = v.w;
        }
        __syncthreads();

#pragma unroll
        for (int k = 0; k < 32; k++) {
            float a[8], b[4];
            *(float4*)&a[0] = *(const float4*)&As[k * 132 + ty * 8];
            *(float4*)&a[4] = *(const float4*)&As[k * 132 + ty * 8 + 4];
            *(float4*)&b[0] = *(const float4*)&Bs[k * 64 + tx * 4];
#pragma unroll
            for (int i = 0; i < 8; i++)
#pragma unroll
                for (int j = 0; j < 4; j++)
                    acc[i][j] = fmaf(a[i], b[j], acc[i][j]);
        }
        __syncthreads();
    }

    float4 bv = *(const float4*)(bias + n0 + tx * 4);
#pragma unroll
    for (int i = 0; i < 8; i++) {
        float4 o;
        o.x = acc[i][0] + bv.x;
        o.y = acc[i][1] + bv.y;
        o.z = acc[i][2] + bv.z;
        o.w = acc[i][3] + bv.w;
        *(float4*)(g_gx + (size_t)(m0 + ty * 8 + i) * G3 + n0 + tx * 4) = o;
    }
}

// ---------------- Phase B: chunked persistent scan ---------------------------
// 128 CTAs x 256 threads, 1 CTA/SM. CTA owns units u0=2*bid, u0+1 (6 gate
// rows) register-resident (packed f32x2). Steps [t0, t1). Global barrier per
// step via per-layer monotone counter (release-atomic + acquire spin).
__global__ __launch_bounds__(256, 1) void gru_scan(
    const float* __restrict__ h0l,
    const float* __restrict__ Whh,
    const float* __restrict__ bhh,
    float* __restrict__ seqout,
    float* __restrict__ hn_out,
    int t0, int t1, int layer)
{
    const int tid = threadIdx.x;
    const int w   = tid >> 5;
    const int l   = tid & 31;
    const int ks  = l & 15;
    const int bh  = l >> 4;
    const int b0  = (w * 2 + bh) * 4;
    const int u0  = blockIdx.x * 2;

    int rows[6];
    rows[0] = u0;       rows[1] = u0 + 1;
    rows[2] = 256 + u0; rows[3] = 257 + u0;
    rows[4] = 512 + u0; rows[5] = 513 + u0;

    // Whh slice packed along k: wk[r][kk*2+p] covers k = kk*64 + ks*4 + {2p,2p+1}
    u64 wk[6][8];
#pragma unroll
    for (int r = 0; r < 6; r++)
#pragma unroll
        for (int kk = 0; kk < 4; kk++) {
            float4 v = *(const float4*)(Whh + (size_t)rows[r] * 256 + kk * 64 + ks * 4);
            wk[r][kk * 2 + 0] = pack2(v.x, v.y);
            wk[r][kk * 2 + 1] = pack2(v.z, v.w);
        }
    float bh6[6];
#pragma unroll
    for (int r = 0; r < 6; r++) bh6[r] = bhh[rows[r]];

    unsigned int* ctr = &g_arrive3[layer];
    const int  j       = ks;
    const bool is_comb = (ks < 4);

    for (int t = t0; t < t1; t++) {
        const float* hsrc = (t == 0) ? h0l
                          : (seqout + (size_t)(t - 1) * (B_SZ * H_SZ));

        // Early loads for combine lanes (hidden under FMA phase)
        u64 gxv0 = 0, gxv1 = 0, gxv2 = 0;
        float hold0 = 0.0f, hold1 = 0.0f;
        if (is_comb) {
            const float* gp = g_gx + ((size_t)t * B_SZ + b0 + j) * G3;
            gxv0 = *(const u64*)(gp + u0);
            gxv1 = *(const u64*)(gp + 256 + u0);
            gxv2 = *(const u64*)(gp + 512 + u0);
            hold0 = __ldcg(hsrc + (b0 + j) * 256 + u0);
            hold1 = __ldcg(hsrc + (b0 + j) * 256 + u0 + 1);
        }

#pragma unroll
        for (int bp = 0; bp < 2; bp++) {            // batch pair {2bp, 2bp+1}
            const int bA = b0 + 2 * bp, bB = bA + 1;
            u64 acc[6][2];
#pragma unroll
            for (int r = 0; r < 6; r++) { acc[r][0] = 0ULL; acc[r][1] = 0ULL; }

            // Pipelined coalesced h loads (16 lanes x 16B contiguous)
            ulonglong2 hA = __ldcg((const ulonglong2*)(hsrc + bA * 256 + ks * 4));
            ulonglong2 hB = __ldcg((const ulonglong2*)(hsrc + bB * 256 + ks * 4));
#pragma unroll
            for (int kk = 0; kk < 4; kk++) {
                ulonglong2 cA = hA, cB = hB;
                if (kk < 3) {
                    hA = __ldcg((const ulonglong2*)(hsrc + bA * 256 + (kk + 1) * 64 + ks * 4));
                    hB = __ldcg((const ulonglong2*)(hsrc + bB * 256 + (kk + 1) * 64 + ks * 4));
                }
#pragma unroll
                for (int r = 0; r < 6; r++) {
                    ffma2(acc[r][0], wk[r][kk * 2 + 0], cA.x);
                    ffma2(acc[r][0], wk[r][kk * 2 + 1], cA.y);
                    ffma2(acc[r][1], wk[r][kk * 2 + 0], cB.x);
                    ffma2(acc[r][1], wk[r][kk * 2 + 1], cB.y);
                }
            }

            // Collapse packed halves, reduce over the 16 k-slices.
            float sA[6], sB[6];
#pragma unroll
            for (int r = 0; r < 6; r++) {
                float2 a = unpack2(acc[r][0]); sA[r] = a.x + a.y;
                float2 b = unpack2(acc[r][1]); sB[r] = b.x + b.y;
            }
#pragma unroll
            for (int off = 1; off < 16; off <<= 1) {
#pragma unroll
                for (int r = 0; r < 6; r++) {
                    sA[r] += __shfl_xor_sync(0xFFFFFFFFu, sA[r], off);
                    sB[r] += __shfl_xor_sync(0xFFFFFFFFu, sB[r], off);
                }
            }

            if (is_comb && (j >> 1) == bp) {
                float s0, s1, s2, s3, s4, s5;
                if (j & 1) { s0=sB[0]; s1=sB[1]; s2=sB[2]; s3=sB[3]; s4=sB[4]; s5=sB[5]; }
                else       { s0=sA[0]; s1=sA[1]; s2=sA[2]; s3=sA[3]; s4=sA[4]; s5=sA[5]; }

                float2 gxr = unpack2(gxv0);
                float2 gxz = unpack2(gxv1);
                float2 gxn = unpack2(gxv2);

                float r0 = fsigmoid(gxr.x + s0 + bh6[0]);
                float z0 = fsigmoid(gxz.x + s2 + bh6[2]);
                float n0 = ftanh(gxn.x + r0 * (s4 + bh6[4]));
                float out0 = (1.0f - z0) * n0 + z0 * hold0;

                float r1 = fsigmoid(gxr.y + s1 + bh6[1]);
                float z1 = fsigmoid(gxz.y + s3 + bh6[3]);
                float n1 = ftanh(gxn.y + r1 * (s5 + bh6[5]));
                float out1 = (1.0f - z1) * n1 + z1 * hold1;

                u64 o = pack2(out0, out1);
                *(u64*)&seqout[((size_t)t * B_SZ + b0 + j) * H_SZ + u0] = o;
                if (t == T_STEPS - 1)
                    *(u64*)&hn_out[(b0 + j) * 256 + u0] = o;
            }
        }

        // Grid barrier: release-add + acquire spin (no full membar.gl / L1 flush)
        __syncthreads();
        if (tid == 0) {
            asm volatile("red.release.gpu.global.add.u32 [%0], 1;"
                         :: "l"(ctr) : "memory");
            const unsigned int target = (unsigned int)(t + 1) * 128u;
            unsigned int v;
            do {
                asm volatile("ld.acquire.gpu.global.u32 %0, [%1];"
                             : "=r"(v) : "l"(ctr) : "memory");
            } while (v < target);
        }
        __syncthreads();
    }
}

// ---------------- launch: pipelined DAG --------------------------------------
extern "C" void kernel_launch(void* const* d_in, const int* in_sizes, int n_in,
                              void* d_out, int out_size)
{
    const float* x   = (const float*)d_in[0];
    const float* h0  = (const float*)d_in[1];
    const float* Wih = (const float*)d_in[2];
    const float* Whh = (const float*)d_in[3];
    const float* bih = (const float*)d_in[4];
    const float* bhh = (const float*)d_in[5];

    float* out     = (float*)d_out;
    float* hn_base = out + (size_t)T_STEPS * B_SZ * H_SZ;

    void* gseq_ptr = nullptr;
    cudaGetSymbolAddress(&gseq_ptr, g_seq);
    float* gseq = (float*)gseq_ptr;

    // Persistent host-side resources (created once, outside capture on the
    // correctness call; reused on the capture call).
    static cudaStream_t s1 = nullptr;
    static cudaEvent_t evFork;
    static cudaEvent_t evG[3][NCHUNK];
    static cudaEvent_t evS[3][NCHUNK];
    if (!s1) {
        cudaStreamCreateWithFlags(&s1, cudaStreamNonBlocking);
        cudaEventCreateWithFlags(&evFork, cudaEventDisableTiming);
        for (int l = 0; l < 3; l++)
            for (int c = 0; c < NCHUNK; c++) {
                cudaEventCreateWithFlags(&evG[l][c], cudaEventDisableTiming);
                cudaEventCreateWithFlags(&evS[l][c], cudaEventDisableTiming);
            }
    }

    const size_t WSTRIDE = (size_t)G3 * 256;
    const size_t HSTRIDE = (size_t)B_SZ * H_SZ;
    const dim3 ggrid(CHUNK_M / 128, G3 / 64);   // (128, 12)

    reset_kernel<<<1, 1>>>();
    cudaEventRecord(evFork, 0);
    cudaStreamWaitEvent(s1, evFork, 0);

    const float* layerA[3]   = { x, gseq, gseq };
    float*       layerOut[3] = { gseq, gseq, out };
    // note: layer0 writes gseq, layer1 reads+writes gseq in place per row
    // (gemm for layer1 chunk c reads rows written by scan0 chunk c; scan1
    //  chunk c overwrites those same rows only after gemm1[c] completed).

    for (int lyr = 0; lyr < 3; lyr++) {
        const float* A   = layerA[lyr];
        float*       so  = layerOut[lyr];
        const float* wih = Wih + lyr * WSTRIDE;
        const float* whh = Whh + lyr * WSTRIDE;
        const float* bi  = bih + lyr * G3;
        const float* bh  = bhh + lyr * G3;
        const float* h0l = h0 + lyr * HSTRIDE;
        float*       hn  = hn_base + lyr * HSTRIDE;

        for (int c = 0; c < NCHUNK; c++) {
            // gemm for this layer's chunk on s1
            if (lyr > 0)
                cudaStreamWaitEvent(s1, evS[lyr - 1][c], 0);
            gemm_gx<<<ggrid, 256, 0, s1>>>(A, wih, bi, c * CHUNK_M);
            cudaEventRecord(evG[lyr][c], s1);

            // scan chunk on the capture (default) stream
            cudaStreamWaitEvent(0, evG[lyr][c], 0);
            gru_scan<<<128, 256>>>(h0l, whh, bh, so, hn,
                                   c * CHUNK_T, (c + 1) * CHUNK_T, lyr);
            cudaEventRecord(evS[lyr][c], 0);
        }
    }
}

// round 6
// speedup vs baseline: 1.5317x; 1.2273x over previous
#include <cuda_runtime.h>

// GRU: T=2048, B=64, IN=256, H=256, L=3
// Output = [seq (2048*64*256) floats][h_n (3*64*256) floats]
//
// R5 design:
//  - gemm_gx: unchanged R4 SGEMM, chunked by timestep range, overlapped on a
//    forked stream (event-gated per chunk).
//  - gru_scan: 128 CTAs = 16 unit-groups x 8 batch-groups. CTA (ug,bg) owns
//    16 hidden units x 8 batches. Weights register-resident (f32x2 packed).
//    Per step: stage 8 batches of h (8KB) into SMEM via __ldcg, FFMA2 over
//    SMEM, 16-lane reduce, gates, store h_t; barrier only among the 16 CTAs
//    of the same batch-group (padded per-group counters, release/acquire).

#define T_STEPS  2048
#define B_SZ     64
#define H_SZ     256
#define G3       768
#define M_TOT    (T_STEPS * B_SZ)
#define NCHUNK   8
#define CHUNK_T  (T_STEPS / NCHUNK)       // 256
#define CHUNK_M  (CHUNK_T * B_SZ)         // 16384

typedef unsigned long long u64;

// ---------------- device scratch (no cudaMalloc allowed) -------------------
__device__ float g_gx[(size_t)M_TOT * G3];     // 402 MB input projections
__device__ float g_seq[(size_t)M_TOT * H_SZ];  // 134 MB inter-layer sequence

struct PaddedCtr { unsigned int v; unsigned int pad[31]; };   // 128B apart
__device__ PaddedCtr g_bar[3][8];                              // [layer][bgrp]

__global__ void reset_kernel() {
    int i = threadIdx.x;
    if (i < 24) g_bar[i / 8][i % 8].v = 0u;
}

// ---------------- packed fp32 helpers ---------------------------------------
__device__ __forceinline__ void ffma2(u64 &d, u64 a, u64 b) {
    asm("fma.rn.f32x2 %0, %1, %2, %0;" : "+l"(d) : "l"(a), "l"(b));
}
__device__ __forceinline__ u64 pack2(float lo, float hi) {
    u64 r; asm("mov.b64 %0, {%1, %2};" : "=l"(r) : "f"(lo), "f"(hi)); return r;
}
__device__ __forceinline__ float2 unpack2(u64 v) {
    float2 r; asm("mov.b64 {%0, %1}, %2;" : "=f"(r.x), "=f"(r.y) : "l"(v)); return r;
}
__device__ __forceinline__ float fsigmoid(float x) {
    float e; asm("ex2.approx.f32 %0, %1;" : "=f"(e) : "f"(-1.4426950408889634f * x));
    float r; asm("rcp.approx.f32 %0, %1;" : "=f"(r) : "f"(1.0f + e));
    return r;
}
__device__ __forceinline__ float ftanh(float x) {
    float y; asm("tanh.approx.f32 %0, %1;" : "=f"(y) : "f"(x)); return y;
}

// ---------------- Phase A: gx GEMM  (chunked) -------------------------------
__global__ __launch_bounds__(256) void gemm_gx(
    const float* __restrict__ A,
    const float* __restrict__ W,
    const float* __restrict__ bias,
    int m_base)
{
    __shared__ __align__(16) float As[32 * 132];
    __shared__ __align__(16) float Bs[32 * 64];

    const int tid = threadIdx.x;
    const int tx  = tid & 15;
    const int ty  = tid >> 4;
    const int m0  = m_base + blockIdx.x * 128;
    const int n0  = blockIdx.y * 64;

    float acc[8][4];
#pragma unroll
    for (int i = 0; i < 8; i++)
#pragma unroll
        for (int j = 0; j < 4; j++) acc[i][j] = 0.0f;

    for (int k0 = 0; k0 < 256; k0 += 32) {
#pragma unroll
        for (int i = 0; i < 4; i++) {
            int f = tid + 256 * i;
            int r = f >> 3, c4 = f & 7;
            float4 v = *(const float4*)(A + (size_t)(m0 + r) * 256 + k0 + c4 * 4);
            As[(c4 * 4 + 0) * 132 + r] = v.x;
            As[(c4 * 4 + 1) * 132 + r] = v.y;
            As[(c4 * 4 + 2) * 132 + r] = v.z;
            As[(c4 * 4 + 3) * 132 + r] = v.w;
        }
#pragma unroll
        for (int i = 0; i < 2; i++) {
            int f = tid + 256 * i;
            int r = f >> 3, c4 = f & 7;
            float4 v = *(const float4*)(W + (size_t)(n0 + r) * 256 + k0 + c4 * 4);
            Bs[(c4 * 4 + 0) * 64 + r] = v.x;
            Bs[(c4 * 4 + 1) * 64 + r] = v.y;
            Bs[(c4 * 4 + 2) * 64 + r] = v.z;
            Bs[(c4 * 4 + 3) * 64 + r] = v.w;
        }
        __syncthreads();

#pragma unroll
        for (int k = 0; k < 32; k++) {
            float a[8], b[4];
            *(float4*)&a[0] = *(const float4*)&As[k * 132 + ty * 8];
            *(float4*)&a[4] = *(const float4*)&As[k * 132 + ty * 8 + 4];
            *(float4*)&b[0] = *(const float4*)&Bs[k * 64 + tx * 4];
#pragma unroll
            for (int i = 0; i < 8; i++)
#pragma unroll
                for (int j = 0; j < 4; j++)
                    acc[i][j] = fmaf(a[i], b[j], acc[i][j]);
        }
        __syncthreads();
    }

    float4 bv = *(const float4*)(bias + n0 + tx * 4);
#pragma unroll
    for (int i = 0; i < 8; i++) {
        float4 o;
        o.x = acc[i][0] + bv.x;
        o.y = acc[i][1] + bv.y;
        o.z = acc[i][2] + bv.z;
        o.w = acc[i][3] + bv.w;
        *(float4*)(g_gx + (size_t)(m0 + ty * 8 + i) * G3 + n0 + tx * 4) = o;
    }
}

// ---------------- Phase B: batch-group decoupled scan ------------------------
// 128 CTAs: bg = bid&7 (8 batches bg*8..+8), ug = bid>>3 (16 units ug*16..+16).
// Warp w owns units u0 = ug*16 + 2w. Lanes: ks = l&15 (k-slice), bh = l>>4
// (local batch half: bh*4..bh*4+3). h for the 8 batches staged in SMEM.
__global__ __launch_bounds__(256, 1) void gru_scan(
    const float* __restrict__ h0l,
    const float* __restrict__ Whh,
    const float* __restrict__ bhh,
    float* __restrict__ seqout,
    float* __restrict__ hn_out,
    int t0, int t1, int layer)
{
    __shared__ __align__(16) float hs[8][256];     // staged h_{t-1}

    const int tid = threadIdx.x;
    const int w   = tid >> 5;
    const int l   = tid & 31;
    const int ks  = l & 15;
    const int bh  = l >> 4;
    const int bg  = blockIdx.x & 7;
    const int ug  = blockIdx.x >> 3;
    const int u0  = ug * 16 + w * 2;
    const int bgrp0 = bg * 8;
    const int b0l   = bh * 4;                      // local batch base (half)

    int rows[6];
    rows[0] = u0;       rows[1] = u0 + 1;
    rows[2] = 256 + u0; rows[3] = 257 + u0;
    rows[4] = 512 + u0; rows[5] = 513 + u0;

    // Whh slice packed along k: wk[r][kk*2+p] covers k = kk*64 + ks*4 + {2p,2p+1}
    u64 wk[6][8];
#pragma unroll
    for (int r = 0; r < 6; r++)
#pragma unroll
        for (int kk = 0; kk < 4; kk++) {
            float4 v = *(const float4*)(Whh + (size_t)rows[r] * 256 + kk * 64 + ks * 4);
            wk[r][kk * 2 + 0] = pack2(v.x, v.y);
            wk[r][kk * 2 + 1] = pack2(v.z, v.w);
        }
    float bh6[6];
#pragma unroll
    for (int r = 0; r < 6; r++) bh6[r] = bhh[rows[r]];

    unsigned int* ctr = &g_bar[layer][bg].v;
    const int  j       = ks;                 // combine lane index within half
    const bool is_comb = (ks < 4);
    const int  bl      = b0l + j;            // local batch (combine lanes)
    const int  gb      = bgrp0 + bl;         // global batch (combine lanes)

    // Prefetch gx for t0.
    u64 gxv0 = 0, gxv1 = 0, gxv2 = 0;
    if (is_comb) {
        const float* gp = g_gx + ((size_t)t0 * B_SZ + gb) * G3;
        gxv0 = *(const u64*)(gp + u0);
        gxv1 = *(const u64*)(gp + 256 + u0);
        gxv2 = *(const u64*)(gp + 512 + u0);
    }

    for (int t = t0; t < t1; t++) {
        // Stage h_{t-1} for our 8 batches: warp w stages batch bgrp0+w.
        {
            const float* hsrc = (t == 0) ? h0l
                              : (seqout + (size_t)(t - 1) * (B_SZ * H_SZ));
            const float4* src = (const float4*)(hsrc + (size_t)(bgrp0 + w) * 256);
            float4 v0 = __ldcg(src + l);
            float4 v1 = __ldcg(src + 32 + l);
            *(float4*)&hs[w][l * 4]       = v0;
            *(float4*)&hs[w][128 + l * 4] = v1;
        }
        __syncthreads();

        float hold0 = 0.0f, hold1 = 0.0f;
        if (is_comb) { hold0 = hs[bl][u0]; hold1 = hs[bl][u0 + 1]; }

#pragma unroll
        for (int bp = 0; bp < 2; bp++) {           // local batch pair
            const int lA = b0l + 2 * bp, lB = lA + 1;
            u64 acc[6][2];
#pragma unroll
            for (int r = 0; r < 6; r++) { acc[r][0] = 0ULL; acc[r][1] = 0ULL; }

#pragma unroll
            for (int kk = 0; kk < 4; kk++) {
                ulonglong2 hA = *(const ulonglong2*)&hs[lA][kk * 64 + ks * 4];
                ulonglong2 hB = *(const ulonglong2*)&hs[lB][kk * 64 + ks * 4];
#pragma unroll
                for (int r = 0; r < 6; r++) {
                    ffma2(acc[r][0], wk[r][kk * 2 + 0], hA.x);
                    ffma2(acc[r][0], wk[r][kk * 2 + 1], hA.y);
                    ffma2(acc[r][1], wk[r][kk * 2 + 0], hB.x);
                    ffma2(acc[r][1], wk[r][kk * 2 + 1], hB.y);
                }
            }

            float sA[6], sB[6];
#pragma unroll
            for (int r = 0; r < 6; r++) {
                float2 a = unpack2(acc[r][0]); sA[r] = a.x + a.y;
                float2 b = unpack2(acc[r][1]); sB[r] = b.x + b.y;
            }
#pragma unroll
            for (int off = 1; off < 16; off <<= 1) {
#pragma unroll
                for (int r = 0; r < 6; r++) {
                    sA[r] += __shfl_xor_sync(0xFFFFFFFFu, sA[r], off);
                    sB[r] += __shfl_xor_sync(0xFFFFFFFFu, sB[r], off);
                }
            }

            if (is_comb && (j >> 1) == bp) {
                float s0, s1, s2, s3, s4, s5;
                if (j & 1) { s0=sB[0]; s1=sB[1]; s2=sB[2]; s3=sB[3]; s4=sB[4]; s5=sB[5]; }
                else       { s0=sA[0]; s1=sA[1]; s2=sA[2]; s3=sA[3]; s4=sA[4]; s5=sA[5]; }

                float2 gxr = unpack2(gxv0);
                float2 gxz = unpack2(gxv1);
                float2 gxn = unpack2(gxv2);

                float r0 = fsigmoid(gxr.x + s0 + bh6[0]);
                float z0 = fsigmoid(gxz.x + s2 + bh6[2]);
                float n0 = ftanh(gxn.x + r0 * (s4 + bh6[4]));
                float out0 = (1.0f - z0) * n0 + z0 * hold0;

                float r1 = fsigmoid(gxr.y + s1 + bh6[1]);
                float z1 = fsigmoid(gxz.y + s3 + bh6[3]);
                float n1 = ftanh(gxn.y + r1 * (s5 + bh6[5]));
                float out1 = (1.0f - z1) * n1 + z1 * hold1;

                u64 o = pack2(out0, out1);
                *(u64*)&seqout[((size_t)t * B_SZ + gb) * H_SZ + u0] = o;
                if (t == T_STEPS - 1)
                    *(u64*)&hn_out[gb * 256 + u0] = o;
            }
        }

        // Prefetch gx for t+1 (independent of the barrier).
        if (is_comb && (t + 1) < t1) {
            const float* gp = g_gx + ((size_t)(t + 1) * B_SZ + gb) * G3;
            gxv0 = *(const u64*)(gp + u0);
            gxv1 = *(const u64*)(gp + 256 + u0);
            gxv2 = *(const u64*)(gp + 512 + u0);
        }

        // Barrier among the 16 CTAs of this batch-group only.
        __syncthreads();
        if (tid == 0) {
            asm volatile("red.release.gpu.global.add.u32 [%0], 1;"
                         :: "l"(ctr) : "memory");
            const unsigned int target = (unsigned int)(t + 1) * 16u;
            unsigned int v;
            do {
                asm volatile("ld.acquire.gpu.global.u32 %0, [%1];"
                             : "=r"(v) : "l"(ctr) : "memory");
            } while (v < target);
        }
        __syncthreads();
    }
}

// ---------------- launch: pipelined DAG --------------------------------------
extern "C" void kernel_launch(void* const* d_in, const int* in_sizes, int n_in,
                              void* d_out, int out_size)
{
    const float* x   = (const float*)d_in[0];
    const float* h0  = (const float*)d_in[1];
    const float* Wih = (const float*)d_in[2];
    const float* Whh = (const float*)d_in[3];
    const float* bih = (const float*)d_in[4];
    const float* bhh = (const float*)d_in[5];

    float* out     = (float*)d_out;
    float* hn_base = out + (size_t)T_STEPS * B_SZ * H_SZ;

    void* gseq_ptr = nullptr;
    cudaGetSymbolAddress(&gseq_ptr, g_seq);
    float* gseq = (float*)gseq_ptr;

    static cudaStream_t s1 = nullptr;
    static cudaEvent_t evFork;
    static cudaEvent_t evG[3][NCHUNK];
    static cudaEvent_t evS[3][NCHUNK];
    if (!s1) {
        cudaStreamCreateWithFlags(&s1, cudaStreamNonBlocking);
        cudaEventCreateWithFlags(&evFork, cudaEventDisableTiming);
        for (int l = 0; l < 3; l++)
            for (int c = 0; c < NCHUNK; c++) {
                cudaEventCreateWithFlags(&evG[l][c], cudaEventDisableTiming);
                cudaEventCreateWithFlags(&evS[l][c], cudaEventDisableTiming);
            }
    }

    const size_t WSTRIDE = (size_t)G3 * 256;
    const size_t HSTRIDE = (size_t)B_SZ * H_SZ;
    const dim3 ggrid(CHUNK_M / 128, G3 / 64);   // (128, 12)

    reset_kernel<<<1, 32>>>();
    cudaEventRecord(evFork, 0);
    cudaStreamWaitEvent(s1, evFork, 0);

    const float* layerA[3]   = { x, gseq, gseq };
    float*       layerOut[3] = { gseq, gseq, out };

    for (int lyr = 0; lyr < 3; lyr++) {
        const float* A   = layerA[lyr];
        float*       so  = layerOut[lyr];
        const float* wih = Wih + lyr * WSTRIDE;
        const float* whh = Whh + lyr * WSTRIDE;
        const float* bi  = bih + lyr * G3;
        const float* bh  = bhh + lyr * G3;
        const float* h0l = h0 + lyr * HSTRIDE;
        float*       hn  = hn_base + lyr * HSTRIDE;

        for (int c = 0; c < NCHUNK; c++) {
            if (lyr > 0)
                cudaStreamWaitEvent(s1, evS[lyr - 1][c], 0);
            gemm_gx<<<ggrid, 256, 0, s1>>>(A, wih, bi, c * CHUNK_M);
            cudaEventRecord(evG[lyr][c], s1);

            cudaStreamWaitEvent(0, evG[lyr][c], 0);
            gru_scan<<<128, 256>>>(h0l, whh, bh, so, hn,
                                   c * CHUNK_T, (c + 1) * CHUNK_T, lyr);
            cudaEventRecord(evS[lyr][c], 0);
        }
    }
}

// round 7
// speedup vs baseline: 1.5800x; 1.0316x over previous
#include <cuda_runtime.h>

// GRU: T=2048, B=64, IN=256, H=256, L=3
// Output = [seq (2048*64*256) floats][h_n (3*64*256) floats]
//
// R6 design:
//  - gemm_gx: unchanged SGEMM, chunked, overlapped on a LOW-PRIORITY stream.
//  - gru_scan: 128 CTAs = 16 unit-groups x 8 batch-groups. Weights in regs
//    (f32x2). Per step: ALL warps poll the batch-group counter (target 16*t),
//    stage h_{t-1} (8KB) into double-buffered SMEM, one syncthreads, FFMA2,
//    16-lane reduce, gates, store h_t, one syncthreads, tid0 release-add.
//  - 3 pad launches so ncu (-s 5 -c 1) profiles the first gru_scan chunk.

#define T_STEPS  2048
#define B_SZ     64
#define H_SZ     256
#define G3       768
#define M_TOT    (T_STEPS * B_SZ)
#define NCHUNK   8
#define CHUNK_T  (T_STEPS / NCHUNK)       // 256
#define CHUNK_M  (CHUNK_T * B_SZ)         // 16384

typedef unsigned long long u64;

// ---------------- device scratch (no cudaMalloc allowed) -------------------
__device__ float g_gx[(size_t)M_TOT * G3];     // 402 MB input projections
__device__ float g_seq[(size_t)M_TOT * H_SZ];  // 134 MB inter-layer sequence

struct PaddedCtr { unsigned int v; unsigned int pad[31]; };   // 128B apart
__device__ PaddedCtr g_bar[3][8];                              // [layer][bgrp]

__global__ void reset_kernel() {
    int i = threadIdx.x;
    if (i < 24) g_bar[i / 8][i % 8].v = 0u;
}

// ---------------- packed fp32 helpers ---------------------------------------
__device__ __forceinline__ void ffma2(u64 &d, u64 a, u64 b) {
    asm("fma.rn.f32x2 %0, %1, %2, %0;" : "+l"(d) : "l"(a), "l"(b));
}
__device__ __forceinline__ u64 pack2(float lo, float hi) {
    u64 r; asm("mov.b64 %0, {%1, %2};" : "=l"(r) : "f"(lo), "f"(hi)); return r;
}
__device__ __forceinline__ float2 unpack2(u64 v) {
    float2 r; asm("mov.b64 {%0, %1}, %2;" : "=f"(r.x), "=f"(r.y) : "l"(v)); return r;
}
__device__ __forceinline__ float fsigmoid(float x) {
    float e; asm("ex2.approx.f32 %0, %1;" : "=f"(e) : "f"(-1.4426950408889634f * x));
    float r; asm("rcp.approx.f32 %0, %1;" : "=f"(r) : "f"(1.0f + e));
    return r;
}
__device__ __forceinline__ float ftanh(float x) {
    float y; asm("tanh.approx.f32 %0, %1;" : "=f"(y) : "f"(x)); return y;
}

// ---------------- Phase A: gx GEMM  (chunked) -------------------------------
__global__ __launch_bounds__(256) void gemm_gx(
    const float* __restrict__ A,
    const float* __restrict__ W,
    const float* __restrict__ bias,
    int m_base)
{
    __shared__ __align__(16) float As[32 * 132];
    __shared__ __align__(16) float Bs[32 * 64];

    const int tid = threadIdx.x;
    const int tx  = tid & 15;
    const int ty  = tid >> 4;
    const int m0  = m_base + blockIdx.x * 128;
    const int n0  = blockIdx.y * 64;

    float acc[8][4];
#pragma unroll
    for (int i = 0; i < 8; i++)
#pragma unroll
        for (int j = 0; j < 4; j++) acc[i][j] = 0.0f;

    for (int k0 = 0; k0 < 256; k0 += 32) {
#pragma unroll
        for (int i = 0; i < 4; i++) {
            int f = tid + 256 * i;
            int r = f >> 3, c4 = f & 7;
            float4 v = *(const float4*)(A + (size_t)(m0 + r) * 256 + k0 + c4 * 4);
            As[(c4 * 4 + 0) * 132 + r] = v.x;
            As[(c4 * 4 + 1) * 132 + r] = v.y;
            As[(c4 * 4 + 2) * 132 + r] = v.z;
            As[(c4 * 4 + 3) * 132 + r] = v.w;
        }
#pragma unroll
        for (int i = 0; i < 2; i++) {
            int f = tid + 256 * i;
            int r = f >> 3, c4 = f & 7;
            float4 v = *(const float4*)(W + (size_t)(n0 + r) * 256 + k0 + c4 * 4);
            Bs[(c4 * 4 + 0) * 64 + r] = v.x;
            Bs[(c4 * 4 + 1) * 64 + r] = v.y;
            Bs[(c4 * 4 + 2) * 64 + r] = v.z;
            Bs[(c4 * 4 + 3) * 64 + r] = v.w;
        }
        __syncthreads();

#pragma unroll
        for (int k = 0; k < 32; k++) {
            float a[8], b[4];
            *(float4*)&a[0] = *(const float4*)&As[k * 132 + ty * 8];
            *(float4*)&a[4] = *(const float4*)&As[k * 132 + ty * 8 + 4];
            *(float4*)&b[0] = *(const float4*)&Bs[k * 64 + tx * 4];
#pragma unroll
            for (int i = 0; i < 8; i++)
#pragma unroll
                for (int j = 0; j < 4; j++)
                    acc[i][j] = fmaf(a[i], b[j], acc[i][j]);
        }
        __syncthreads();
    }

    float4 bv = *(const float4*)(bias + n0 + tx * 4);
#pragma unroll
    for (int i = 0; i < 8; i++) {
        float4 o;
        o.x = acc[i][0] + bv.x;
        o.y = acc[i][1] + bv.y;
        o.z = acc[i][2] + bv.z;
        o.w = acc[i][3] + bv.w;
        *(float4*)(g_gx + (size_t)(m0 + ty * 8 + i) * G3 + n0 + tx * 4) = o;
    }
}

// ---------------- Phase B: batch-group decoupled scan ------------------------
// 128 CTAs: bg = bid&7 (batches bg*8..+8), ug = bid>>3 (units ug*16..+16).
// Warp w owns units u0 = ug*16 + 2w. Lanes: ks = l&15 (k-slice), bh = l>>4.
// Step: all-warp poll (counter >= 16*t) -> stage h into hs[t&1] -> sync ->
// FFMA2 -> reduce -> gates/store -> sync -> tid0 release-add.
__global__ __launch_bounds__(256, 1) void gru_scan(
    const float* __restrict__ h0l,
    const float* __restrict__ Whh,
    const float* __restrict__ bhh,
    float* __restrict__ seqout,
    float* __restrict__ hn_out,
    int t0, int t1, int layer)
{
    __shared__ __align__(16) float hs[2][8][256];   // double-buffered staged h

    const int tid = threadIdx.x;
    const int w   = tid >> 5;
    const int l   = tid & 31;
    const int ks  = l & 15;
    const int bh  = l >> 4;
    const int bg  = blockIdx.x & 7;
    const int ug  = blockIdx.x >> 3;
    const int u0  = ug * 16 + w * 2;
    const int bgrp0 = bg * 8;
    const int b0l   = bh * 4;

    int rows[6];
    rows[0] = u0;       rows[1] = u0 + 1;
    rows[2] = 256 + u0; rows[3] = 257 + u0;
    rows[4] = 512 + u0; rows[5] = 513 + u0;

    u64 wk[6][8];
#pragma unroll
    for (int r = 0; r < 6; r++)
#pragma unroll
        for (int kk = 0; kk < 4; kk++) {
            float4 v = *(const float4*)(Whh + (size_t)rows[r] * 256 + kk * 64 + ks * 4);
            wk[r][kk * 2 + 0] = pack2(v.x, v.y);
            wk[r][kk * 2 + 1] = pack2(v.z, v.w);
        }
    float bh6[6];
#pragma unroll
    for (int r = 0; r < 6; r++) bh6[r] = bhh[rows[r]];

    unsigned int* ctr = &g_bar[layer][bg].v;
    const int  j       = ks;
    const bool is_comb = (ks < 4);
    const int  bl      = b0l + j;
    const int  gb      = bgrp0 + bl;

    // Prefetch gx for t0.
    u64 gxv0 = 0, gxv1 = 0, gxv2 = 0;
    if (is_comb) {
        const float* gp = g_gx + ((size_t)t0 * B_SZ + gb) * G3;
        gxv0 = *(const u64*)(gp + u0);
        gxv1 = *(const u64*)(gp + 256 + u0);
        gxv2 = *(const u64*)(gp + 512 + u0);
    }

    for (int t = t0; t < t1; t++) {
        const int cur = t & 1;

        // 1) All warps poll: step t needs all 16 CTAs done with step t-1.
        if (t > 0) {
            const unsigned int target = (unsigned int)t * 16u;
            unsigned int v;
            do {
                asm volatile("ld.acquire.gpu.global.u32 %0, [%1];"
                             : "=r"(v) : "l"(ctr) : "memory");
            } while (v < target);
        }

        // 2) Stage h_{t-1}: warp w stages batch bgrp0+w into hs[cur].
        {
            const float* hsrc = (t == 0) ? h0l
                              : (seqout + (size_t)(t - 1) * (B_SZ * H_SZ));
            const float4* src = (const float4*)(hsrc + (size_t)(bgrp0 + w) * 256);
            float4 v0 = __ldcg(src + l);
            float4 v1 = __ldcg(src + 32 + l);
            *(float4*)&hs[cur][w][l * 4]       = v0;
            *(float4*)&hs[cur][w][128 + l * 4] = v1;
        }
        __syncthreads();

        float hold0 = 0.0f, hold1 = 0.0f;
        if (is_comb) { hold0 = hs[cur][bl][u0]; hold1 = hs[cur][bl][u0 + 1]; }

#pragma unroll
        for (int bp = 0; bp < 2; bp++) {
            const int lA = b0l + 2 * bp, lB = lA + 1;
            u64 acc[6][2];
#pragma unroll
            for (int r = 0; r < 6; r++) { acc[r][0] = 0ULL; acc[r][1] = 0ULL; }

#pragma unroll
            for (int kk = 0; kk < 4; kk++) {
                ulonglong2 hA = *(const ulonglong2*)&hs[cur][lA][kk * 64 + ks * 4];
                ulonglong2 hB = *(const ulonglong2*)&hs[cur][lB][kk * 64 + ks * 4];
#pragma unroll
                for (int r = 0; r < 6; r++) {
                    ffma2(acc[r][0], wk[r][kk * 2 + 0], hA.x);
                    ffma2(acc[r][0], wk[r][kk * 2 + 1], hA.y);
                    ffma2(acc[r][1], wk[r][kk * 2 + 0], hB.x);
                    ffma2(acc[r][1], wk[r][kk * 2 + 1], hB.y);
                }
            }

            float sA[6], sB[6];
#pragma unroll
            for (int r = 0; r < 6; r++) {
                float2 a = unpack2(acc[r][0]); sA[r] = a.x + a.y;
                float2 b = unpack2(acc[r][1]); sB[r] = b.x + b.y;
            }
#pragma unroll
            for (int off = 1; off < 16; off <<= 1) {
#pragma unroll
                for (int r = 0; r < 6; r++) {
                    sA[r] += __shfl_xor_sync(0xFFFFFFFFu, sA[r], off);
                    sB[r] += __shfl_xor_sync(0xFFFFFFFFu, sB[r], off);
                }
            }

            if (is_comb && (j >> 1) == bp) {
                float s0, s1, s2, s3, s4, s5;
                if (j & 1) { s0=sB[0]; s1=sB[1]; s2=sB[2]; s3=sB[3]; s4=sB[4]; s5=sB[5]; }
                else       { s0=sA[0]; s1=sA[1]; s2=sA[2]; s3=sA[3]; s4=sA[4]; s5=sA[5]; }

                float2 gxr = unpack2(gxv0);
                float2 gxz = unpack2(gxv1);
                float2 gxn = unpack2(gxv2);

                float r0 = fsigmoid(gxr.x + s0 + bh6[0]);
                float z0 = fsigmoid(gxz.x + s2 + bh6[2]);
                float n0 = ftanh(gxn.x + r0 * (s4 + bh6[4]));
                float out0 = (1.0f - z0) * n0 + z0 * hold0;

                float r1 = fsigmoid(gxr.y + s1 + bh6[1]);
                float z1 = fsigmoid(gxz.y + s3 + bh6[3]);
                float n1 = ftanh(gxn.y + r1 * (s5 + bh6[5]));
                float out1 = (1.0f - z1) * n1 + z1 * hold1;

                u64 o = pack2(out0, out1);
                *(u64*)&seqout[((size_t)t * B_SZ + gb) * H_SZ + u0] = o;
                if (t == T_STEPS - 1)
                    *(u64*)&hn_out[gb * 256 + u0] = o;
            }
        }

        // Prefetch gx for t+1 (off the critical path).
        if (is_comb && (t + 1) < t1) {
            const float* gp = g_gx + ((size_t)(t + 1) * B_SZ + gb) * G3;
            gxv0 = *(const u64*)(gp + u0);
            gxv1 = *(const u64*)(gp + 256 + u0);
            gxv2 = *(const u64*)(gp + 512 + u0);
        }

        // 3) Release: this CTA's h_t stores are done.
        __syncthreads();
        if (tid == 0)
            asm volatile("red.release.gpu.global.add.u32 [%0], 1;"
                         :: "l"(ctr) : "memory");
    }
}

// ---------------- launch: pipelined DAG --------------------------------------
extern "C" void kernel_launch(void* const* d_in, const int* in_sizes, int n_in,
                              void* d_out, int out_size)
{
    const float* x   = (const float*)d_in[0];
    const float* h0  = (const float*)d_in[1];
    const float* Wih = (const float*)d_in[2];
    const float* Whh = (const float*)d_in[3];
    const float* bih = (const float*)d_in[4];
    const float* bhh = (const float*)d_in[5];

    float* out     = (float*)d_out;
    float* hn_base = out + (size_t)T_STEPS * B_SZ * H_SZ;

    void* gseq_ptr = nullptr;
    cudaGetSymbolAddress(&gseq_ptr, g_seq);
    float* gseq = (float*)gseq_ptr;

    static cudaStream_t s1 = nullptr;
    static cudaEvent_t evFork;
    static cudaEvent_t evG[3][NCHUNK];
    static cudaEvent_t evS[3][NCHUNK];
    if (!s1) {
        int loPri = 0, hiPri = 0;
        cudaDeviceGetStreamPriorityRange(&loPri, &hiPri);
        // loPri = numerically-largest = LOWEST priority: gemm must yield to scan
        cudaStreamCreateWithPriority(&s1, cudaStreamNonBlocking, loPri);
        cudaEventCreateWithFlags(&evFork, cudaEventDisableTiming);
        for (int l = 0; l < 3; l++)
            for (int c = 0; c < NCHUNK; c++) {
                cudaEventCreateWithFlags(&evG[l][c], cudaEventDisableTiming);
                cudaEventCreateWithFlags(&evS[l][c], cudaEventDisableTiming);
            }
    }

    const size_t WSTRIDE = (size_t)G3 * 256;
    const size_t HSTRIDE = (size_t)B_SZ * H_SZ;
    const dim3 ggrid(CHUNK_M / 128, G3 / 64);   // (128, 12)

    // Launches 0-3: reset + pads so ncu (-s 5) profiles the first gru_scan.
    reset_kernel<<<1, 32>>>();
    reset_kernel<<<1, 32>>>();
    reset_kernel<<<1, 32>>>();
    reset_kernel<<<1, 32>>>();
    cudaEventRecord(evFork, 0);
    cudaStreamWaitEvent(s1, evFork, 0);

    const float* layerA[3]   = { x, gseq, gseq };
    float*       layerOut[3] = { gseq, gseq, out };

    for (int lyr = 0; lyr < 3; lyr++) {
        const float* A   = layerA[lyr];
        float*       so  = layerOut[lyr];
        const float* wih = Wih + lyr * WSTRIDE;
        const float* whh = Whh + lyr * WSTRIDE;
        const float* bi  = bih + lyr * G3;
        const float* bh  = bhh + lyr * G3;
        const float* h0l = h0 + lyr * HSTRIDE;
        float*       hn  = hn_base + lyr * HSTRIDE;

        for (int c = 0; c < NCHUNK; c++) {
            if (lyr > 0)
                cudaStreamWaitEvent(s1, evS[lyr - 1][c], 0);
            gemm_gx<<<ggrid, 256, 0, s1>>>(A, wih, bi, c * CHUNK_M);
            cudaEventRecord(evG[lyr][c], s1);

            cudaStreamWaitEvent(0, evG[lyr][c], 0);
            gru_scan<<<128, 256>>>(h0l, whh, bh, so, hn,
                                   c * CHUNK_T, (c + 1) * CHUNK_T, lyr);
            cudaEventRecord(evS[lyr][c], 0);
        }
    }
}